// round 6
// baseline (speedup 1.0000x reference)
#include <cuda_runtime.h>
#include <cstdint>

#define NN 50000
#define NM 4
#define DD 128
#define NE 800000
#define ALPHA 0.05f
#define EPS 1e-5f

#define NPC 8                      // nodes per CTA
#define NCTA (NN / NPC)            // 6250
#define THREADS 256

// ---------------------------------------------------------------------------
// Device globals (no runtime allocation)
// ---------------------------------------------------------------------------
__device__ int   g_count[NN];
__device__ int   g_off[NN + 1];
__device__ int   g_cursor[NN];
__device__ int   g_src_s[NE];
__device__ float g_w_s[NE];
__device__ int   g_bsum[64];
__device__ int   g_bbase[64];

// ---------------------------------------------------------------------------
// mbarrier helpers
// ---------------------------------------------------------------------------
__device__ __forceinline__ uint32_t smem_u32(const void* p) {
    uint32_t a;
    asm("{ .reg .u64 t; cvta.to.shared.u64 t, %1; cvt.u32.u64 %0, t; }" : "=r"(a) : "l"(p));
    return a;
}
__device__ __forceinline__ void mbar_init(uint32_t addr, uint32_t cnt) {
    asm volatile("mbarrier.init.shared.b64 [%0], %1;" :: "r"(addr), "r"(cnt) : "memory");
}
__device__ __forceinline__ void mbar_arrive(uint32_t addr) {
    asm volatile("mbarrier.arrive.shared.b64 _, [%0];" :: "r"(addr) : "memory");
}
__device__ __forceinline__ void mbar_wait(uint32_t addr, uint32_t parity) {
    asm volatile(
        "{\n\t.reg .pred P;\n"
        "W%=:\n\tmbarrier.try_wait.parity.acquire.cta.shared::cta.b64 P, [%0], %1, 0x989680;\n"
        "\t@P bra D%=;\n\tbra W%=;\nD%=:\n\t}"
        :: "r"(addr), "r"(parity) : "memory");
}

// ---------------------------------------------------------------------------
// CSR build (unchanged, known good)
// ---------------------------------------------------------------------------
__global__ void zero_counts_kernel() {
    int i = blockIdx.x * blockDim.x + threadIdx.x;
    if (i < NN) g_count[i] = 0;
}
__global__ void hist_kernel(const int* __restrict__ dst) {
    int e = blockIdx.x * blockDim.x + threadIdx.x;
    if (e < NE) atomicAdd(&g_count[dst[e]], 1);
}
__global__ void __launch_bounds__(1024) scan1_kernel() {
    __shared__ int s[1024];
    int i = blockIdx.x * 1024 + threadIdx.x;
    int v = (i < NN) ? g_count[i] : 0;
    s[threadIdx.x] = v;
    __syncthreads();
#pragma unroll
    for (int o = 1; o < 1024; o <<= 1) {
        int t = (threadIdx.x >= o) ? s[threadIdx.x - o] : 0;
        __syncthreads();
        s[threadIdx.x] += t;
        __syncthreads();
    }
    if (i < NN) g_off[i] = s[threadIdx.x] - v;
    if (threadIdx.x == 1023) g_bsum[blockIdx.x] = s[1023];
}
__global__ void scan2_kernel(int nblocks) {
    __shared__ int s[64];
    int v = (threadIdx.x < nblocks) ? g_bsum[threadIdx.x] : 0;
    s[threadIdx.x] = v;
    __syncthreads();
#pragma unroll
    for (int o = 1; o < 64; o <<= 1) {
        int t = (threadIdx.x >= o) ? s[threadIdx.x - o] : 0;
        __syncthreads();
        s[threadIdx.x] += t;
        __syncthreads();
    }
    g_bbase[threadIdx.x] = s[threadIdx.x] - v;
    if (threadIdx.x == 0) g_off[NN] = s[63];
}
__global__ void __launch_bounds__(1024) scan3_kernel() {
    int i = blockIdx.x * 1024 + threadIdx.x;
    if (i < NN) {
        int o = g_off[i] + g_bbase[blockIdx.x];
        g_off[i] = o;
        g_cursor[i] = o;
    }
}
__global__ void fill_csr_kernel(const int* __restrict__ src,
                                const int* __restrict__ dst,
                                const float* __restrict__ w) {
    int e = blockIdx.x * blockDim.x + threadIdx.x;
    if (e < NE) {
        int t = dst[e];
        int pos = atomicAdd(&g_cursor[t], 1);
        g_src_s[pos] = src[e];
        g_w_s[pos]  = w[e];
    }
}

// ---------------------------------------------------------------------------
// Warp-specialized fused kernel. 256 threads, NPC nodes per CTA.
//   Warps 0-3 (producers): gather agg rows into a 2-deep smem ring.
//   Warps 4-7 (consumers): k-split GEMM + cross-warp reduce + residual + LN.
// Handoff: full/empty mbarrier pairs (count=128 each side).
// ---------------------------------------------------------------------------
__global__ void __launch_bounds__(THREADS, 1) fused_kernel(
    const float4* __restrict__ x4,     // multimodal rows = 128 f4
    const float*  __restrict__ xf,     // multimodal flat
    const float4* __restrict__ W4,     // W rows = 32 f4
    const float4* __restrict__ gamma4,
    const float4* __restrict__ beta4,
    float4* __restrict__ out4)         // [N*M, 32] f4
{
    __shared__ __align__(16) float  s_agg[2][NM * DD];   // 4 KB ring
    __shared__ __align__(16) float4 s_part[4][NM][32];   // 8 KB
    __shared__ __align__(8)  unsigned long long mb[4];   // full0,empty0,full1,empty1

    const int tid  = threadIdx.x;
    const int wid  = tid >> 5;
    const int lane = tid & 31;
    const int node0 = blockIdx.x * NPC;

    const uint32_t mb_base = smem_u32(&mb[0]);
    if (tid == 0) {
        mbar_init(mb_base + 0, 128);   // full  stage 0
        mbar_init(mb_base + 8, 128);   // empty stage 0
        mbar_init(mb_base + 16, 128);  // full  stage 1
        mbar_init(mb_base + 24, 128);  // empty stage 1
    }
    __syncthreads();

    if (wid < 4) {
        // ================= producers =================
        const int ptid = tid;   // 0..127; one float4 slice of the 512-f row
        for (int i = 0; i < NPC; i++) {
            const int stage = i & 1;
            const uint32_t full_b  = mb_base + stage * 16;
            const uint32_t empty_b = full_b + 8;
            mbar_wait(empty_b, 1u ^ ((i >> 1) & 1));

            const int node = node0 + i;
            const int b = g_off[node], e = g_off[node + 1];
            float4 acc = make_float4(0.f, 0.f, 0.f, 0.f);
            int q = b;
            for (; q + 1 < e; q += 2) {
                int   s0 = __ldg(&g_src_s[q]);
                int   s1 = __ldg(&g_src_s[q + 1]);
                float w0 = __ldg(&g_w_s[q]);
                float w1 = __ldg(&g_w_s[q + 1]);
                float4 v0 = __ldg(&x4[(size_t)s0 * 128 + ptid]);
                float4 v1 = __ldg(&x4[(size_t)s1 * 128 + ptid]);
                acc.x = fmaf(w0, v0.x, acc.x); acc.y = fmaf(w0, v0.y, acc.y);
                acc.z = fmaf(w0, v0.z, acc.z); acc.w = fmaf(w0, v0.w, acc.w);
                acc.x = fmaf(w1, v1.x, acc.x); acc.y = fmaf(w1, v1.y, acc.y);
                acc.z = fmaf(w1, v1.z, acc.z); acc.w = fmaf(w1, v1.w, acc.w);
            }
            if (q < e) {
                int   s0 = __ldg(&g_src_s[q]);
                float w0 = __ldg(&g_w_s[q]);
                float4 v0 = __ldg(&x4[(size_t)s0 * 128 + ptid]);
                acc.x = fmaf(w0, v0.x, acc.x); acc.y = fmaf(w0, v0.y, acc.y);
                acc.z = fmaf(w0, v0.z, acc.z); acc.w = fmaf(w0, v0.w, acc.w);
            }
            *reinterpret_cast<float4*>(&s_agg[stage][ptid * 4]) = acc;
            mbar_arrive(full_b);
        }
    } else {
        // ================= consumers =================
        const int cwid = wid - 4;   // 0..3
        for (int i = 0; i < NPC; i++) {
            const int stage = i & 1;
            const uint32_t full_b  = mb_base + stage * 16;
            const uint32_t empty_b = full_b + 8;
            mbar_wait(full_b, (i >> 1) & 1);

            // ---- k-split GEMM: warp cwid covers k in [32*cwid, 32*cwid+32) ----
            float4 p0 = make_float4(0.f, 0.f, 0.f, 0.f);
            float4 p1 = make_float4(0.f, 0.f, 0.f, 0.f);
            float4 p2 = make_float4(0.f, 0.f, 0.f, 0.f);
            float4 p3 = make_float4(0.f, 0.f, 0.f, 0.f);
            const float* agg = &s_agg[stage][0];
            const int kbase = cwid * 32;
#pragma unroll 8
            for (int kk = 0; kk < 32; kk++) {
                const int k = kbase + kk;
                float4 wv = __ldg(&W4[k * 32 + lane]);
                float a0 = agg[0 * DD + k];
                float a1 = agg[1 * DD + k];
                float a2 = agg[2 * DD + k];
                float a3 = agg[3 * DD + k];
                p0.x = fmaf(a0, wv.x, p0.x); p0.y = fmaf(a0, wv.y, p0.y);
                p0.z = fmaf(a0, wv.z, p0.z); p0.w = fmaf(a0, wv.w, p0.w);
                p1.x = fmaf(a1, wv.x, p1.x); p1.y = fmaf(a1, wv.y, p1.y);
                p1.z = fmaf(a1, wv.z, p1.z); p1.w = fmaf(a1, wv.w, p1.w);
                p2.x = fmaf(a2, wv.x, p2.x); p2.y = fmaf(a2, wv.y, p2.y);
                p2.z = fmaf(a2, wv.z, p2.z); p2.w = fmaf(a2, wv.w, p2.w);
                p3.x = fmaf(a3, wv.x, p3.x); p3.y = fmaf(a3, wv.y, p3.y);
                p3.z = fmaf(a3, wv.z, p3.z); p3.w = fmaf(a3, wv.w, p3.w);
            }
            mbar_arrive(empty_b);   // s_agg[stage] fully consumed

            s_part[cwid][0][lane] = p0;
            s_part[cwid][1][lane] = p1;
            s_part[cwid][2][lane] = p2;
            s_part[cwid][3][lane] = p3;
            asm volatile("bar.sync 1, 128;" ::: "memory");

            // ---- reduce partials; warp cwid finishes modality cwid ----
            float4 q0 = s_part[0][cwid][lane];
            float4 q1 = s_part[1][cwid][lane];
            float4 q2 = s_part[2][cwid][lane];
            float4 q3 = s_part[3][cwid][lane];
            float a0 = (q0.x + q1.x) + (q2.x + q3.x);
            float a1 = (q0.y + q1.y) + (q2.y + q3.y);
            float a2 = (q0.z + q1.z) + (q2.z + q3.z);
            float a3 = (q0.w + q1.w) + (q2.w + q3.w);

            const size_t rowg = (size_t)(node0 + i) * NM + cwid;
            float4 xv = __ldg(reinterpret_cast<const float4*>(xf) + rowg * 32 + lane);

            float y0 = fmaf(ALPHA, a0, xv.x);
            float y1 = fmaf(ALPHA, a1, xv.y);
            float y2 = fmaf(ALPHA, a2, xv.z);
            float y3 = fmaf(ALPHA, a3, xv.w);

            float s  = y0 + y1 + y2 + y3;
            float ss = y0 * y0 + y1 * y1 + y2 * y2 + y3 * y3;
#pragma unroll
            for (int o = 16; o > 0; o >>= 1) {
                s  += __shfl_xor_sync(0xFFFFFFFFu, s, o);
                ss += __shfl_xor_sync(0xFFFFFFFFu, ss, o);
            }
            const float inv_d = 1.f / (float)DD;
            float mu  = s * inv_d;
            float var = ss * inv_d - mu * mu;
            float inv = rsqrtf(var + EPS);

            float4 g = __ldg(&gamma4[lane]);
            float4 b = __ldg(&beta4[lane]);
            float4 o4;
            o4.x = fmaf((y0 - mu) * inv, g.x, b.x);
            o4.y = fmaf((y1 - mu) * inv, g.y, b.y);
            o4.z = fmaf((y2 - mu) * inv, g.z, b.z);
            o4.w = fmaf((y3 - mu) * inv, g.w, b.w);
            out4[rowg * 32 + lane] = o4;

            asm volatile("bar.sync 1, 128;" ::: "memory");  // s_part reuse guard
        }
    }
}

// ---------------------------------------------------------------------------
extern "C" void kernel_launch(void* const* d_in, const int* in_sizes, int n_in,
                              void* d_out, int out_size) {
    const float* multimodal = (const float*)d_in[0];  // [N, M, D] fp32
    const int*   edge_src   = (const int*)d_in[1];
    const int*   edge_dst   = (const int*)d_in[2];
    const float* edge_w     = (const float*)d_in[3];
    const float* W          = (const float*)d_in[4];
    const float* gamma      = (const float*)d_in[5];
    const float* beta       = (const float*)d_in[6];
    float* out = (float*)d_out;

    const int SCAN_BLOCKS = (NN + 1023) / 1024;  // 49

    zero_counts_kernel<<<(NN + 255) / 256, 256>>>();
    hist_kernel<<<(NE + 255) / 256, 256>>>(edge_dst);
    scan1_kernel<<<SCAN_BLOCKS, 1024>>>();
    scan2_kernel<<<1, 64>>>(SCAN_BLOCKS);
    scan3_kernel<<<SCAN_BLOCKS, 1024>>>();
    fill_csr_kernel<<<(NE + 255) / 256, 256>>>(edge_src, edge_dst, edge_w);

    fused_kernel<<<NCTA, THREADS>>>(
        (const float4*)multimodal, multimodal,
        (const float4*)W, (const float4*)gamma, (const float4*)beta,
        (float4*)out);
}

// round 7
// speedup vs baseline: 1.4116x; 1.4116x over previous
#include <cuda_runtime.h>
#include <cuda_bf16.h>
#include <cstdint>

#define NN 50000
#define NM 4
#define DD 128
#define NE 800000
#define ALPHA 0.05f
#define EPS 1e-5f

#define NPC 8                       // nodes per CTA
#define ROWS 32                     // NPC * NM
#define NCTA (NN / NPC)             // 6250
#define THREADS 256

// padded strides (elements)
#define AST 136                     // A row stride in bf16 (68 u32 words)
#define BST 136                     // B^T row stride in bf16
#define CST 132                     // C row stride in f32

// dynamic smem layout (bytes)
#define OFF_AHI 0
#define OFF_ALO (OFF_AHI + ROWS * AST * 2)          // 8704
#define OFF_BHI (OFF_ALO + ROWS * AST * 2)          // 17408
#define OFF_BLO (OFF_BHI + DD * BST * 2)            // 52224
#define OFF_C   (OFF_BLO + DD * BST * 2)            // 87040
#define SMEM_TOTAL (OFF_C + ROWS * CST * 4)         // 103936

// ---------------------------------------------------------------------------
// Device globals
// ---------------------------------------------------------------------------
__device__ int   g_count[NN];
__device__ int   g_off[NN + 1];
__device__ int   g_cursor[NN];
__device__ int   g_src_s[NE];
__device__ float g_w_s[NE];
__device__ int   g_bsum[64];
__device__ int   g_bbase[64];
__device__ __align__(16) __nv_bfloat16 g_Bt_hi[DD * BST];  // W^T hi, padded
__device__ __align__(16) __nv_bfloat16 g_Bt_lo[DD * BST];  // W^T lo

// ---------------------------------------------------------------------------
// CSR build (known good)
// ---------------------------------------------------------------------------
__global__ void zero_counts_kernel() {
    int i = blockIdx.x * blockDim.x + threadIdx.x;
    if (i < NN) g_count[i] = 0;
}
__global__ void hist_kernel(const int* __restrict__ dst) {
    int e = blockIdx.x * blockDim.x + threadIdx.x;
    if (e < NE) atomicAdd(&g_count[dst[e]], 1);
}
__global__ void __launch_bounds__(1024) scan1_kernel() {
    __shared__ int s[1024];
    int i = blockIdx.x * 1024 + threadIdx.x;
    int v = (i < NN) ? g_count[i] : 0;
    s[threadIdx.x] = v;
    __syncthreads();
#pragma unroll
    for (int o = 1; o < 1024; o <<= 1) {
        int t = (threadIdx.x >= o) ? s[threadIdx.x - o] : 0;
        __syncthreads();
        s[threadIdx.x] += t;
        __syncthreads();
    }
    if (i < NN) g_off[i] = s[threadIdx.x] - v;
    if (threadIdx.x == 1023) g_bsum[blockIdx.x] = s[1023];
}
__global__ void scan2_kernel(int nblocks) {
    __shared__ int s[64];
    int v = (threadIdx.x < nblocks) ? g_bsum[threadIdx.x] : 0;
    s[threadIdx.x] = v;
    __syncthreads();
#pragma unroll
    for (int o = 1; o < 64; o <<= 1) {
        int t = (threadIdx.x >= o) ? s[threadIdx.x - o] : 0;
        __syncthreads();
        s[threadIdx.x] += t;
        __syncthreads();
    }
    g_bbase[threadIdx.x] = s[threadIdx.x] - v;
    if (threadIdx.x == 0) g_off[NN] = s[63];
}
__global__ void __launch_bounds__(1024) scan3_kernel() {
    int i = blockIdx.x * 1024 + threadIdx.x;
    if (i < NN) {
        int o = g_off[i] + g_bbase[blockIdx.x];
        g_off[i] = o;
        g_cursor[i] = o;
    }
}
__global__ void fill_csr_kernel(const int* __restrict__ src,
                                const int* __restrict__ dst,
                                const float* __restrict__ w) {
    int e = blockIdx.x * blockDim.x + threadIdx.x;
    if (e < NE) {
        int t = dst[e];
        int pos = atomicAdd(&g_cursor[t], 1);
        g_src_s[pos] = src[e];
        g_w_s[pos]  = w[e];
    }
}

// ---------------------------------------------------------------------------
// Pack B = W^T into hi/lo bf16, padded [n][k] layout (k contiguous)
// ---------------------------------------------------------------------------
__global__ void pack_B_kernel(const float* __restrict__ W) {
    int idx = blockIdx.x * blockDim.x + threadIdx.x;   // n*BST + k
    if (idx < DD * BST) {
        int n = idx / BST, k = idx % BST;
        float v = (k < DD) ? W[k * DD + n] : 0.f;
        __nv_bfloat16 hi = __float2bfloat16(v);
        float rem = v - __bfloat162float(hi);
        g_Bt_hi[idx] = hi;
        g_Bt_lo[idx] = __float2bfloat16(rem);
    }
}

// ---------------------------------------------------------------------------
// mma.sync bf16 (baseline sm_80+ feature — compiles on plain compute_103)
// ---------------------------------------------------------------------------
__device__ __forceinline__ void mma_bf16(float c[4],
                                         uint32_t a0, uint32_t a1, uint32_t a2, uint32_t a3,
                                         uint32_t b0, uint32_t b1) {
    asm volatile(
        "mma.sync.aligned.m16n8k16.row.col.f32.bf16.bf16.f32 "
        "{%0,%1,%2,%3}, {%4,%5,%6,%7}, {%8,%9}, {%0,%1,%2,%3};"
        : "+f"(c[0]), "+f"(c[1]), "+f"(c[2]), "+f"(c[3])
        : "r"(a0), "r"(a1), "r"(a2), "r"(a3), "r"(b0), "r"(b1));
}

__device__ __forceinline__ uint32_t pack_bf16(float x, float y) {
    __nv_bfloat162 p = __floats2bfloat162_rn(x, y);
    return *reinterpret_cast<uint32_t*>(&p);
}

// ---------------------------------------------------------------------------
// Fused: gather (fp32) -> bf16-split A tile -> mma.sync GEMM -> residual+LN
// One CTA per 8 nodes (32 rows), 256 threads, ~104 KB dynamic smem.
// ---------------------------------------------------------------------------
__global__ void __launch_bounds__(THREADS) fused_kernel(
    const float4* __restrict__ x4,     // multimodal rows = 128 f4
    const float*  __restrict__ xf,
    const float4* __restrict__ gamma4,
    const float4* __restrict__ beta4,
    float4* __restrict__ out4)
{
    extern __shared__ char sm[];
    uint32_t* Ah = reinterpret_cast<uint32_t*>(sm + OFF_AHI);   // [ROWS][68] words
    uint32_t* Al = reinterpret_cast<uint32_t*>(sm + OFF_ALO);
    uint32_t* Bh = reinterpret_cast<uint32_t*>(sm + OFF_BHI);   // [128][68] words
    uint32_t* Bl = reinterpret_cast<uint32_t*>(sm + OFF_BLO);
    float*    Cf = reinterpret_cast<float*>(sm + OFF_C);        // [ROWS][132]

    const int cta  = blockIdx.x;
    const int tid  = threadIdx.x;
    const int wid  = tid >> 5;
    const int lane = tid & 31;

    // ---- copy B^T hi/lo into smem (uint4) ----
    {
        const uint4* sh = reinterpret_cast<const uint4*>(g_Bt_hi);
        const uint4* sl = reinterpret_cast<const uint4*>(g_Bt_lo);
        uint4* dh = reinterpret_cast<uint4*>(sm + OFF_BHI);
        uint4* dl = reinterpret_cast<uint4*>(sm + OFF_BLO);
        const int n16 = DD * BST * 2 / 16;   // 2176
        for (int i = tid; i < n16; i += THREADS) { dh[i] = sh[i]; dl[i] = sl[i]; }
    }

    // ---- Phase 1: gather. group g (=tid>>7) handles nodes g*4..g*4+3 ----
    const int grp = tid >> 7;
    const int t4  = tid & 127;
    for (int jj = 0; jj < 4; jj++) {
        const int nl   = grp * 4 + jj;            // local node 0..7
        const int node = cta * NPC + nl;
        const int b = g_off[node], e = g_off[node + 1];
        float4 acc = make_float4(0.f, 0.f, 0.f, 0.f);
        int q = b;
        for (; q + 1 < e; q += 2) {
            int   s0 = __ldg(&g_src_s[q]);
            int   s1 = __ldg(&g_src_s[q + 1]);
            float w0 = __ldg(&g_w_s[q]);
            float w1 = __ldg(&g_w_s[q + 1]);
            float4 v0 = __ldg(&x4[(size_t)s0 * 128 + t4]);
            float4 v1 = __ldg(&x4[(size_t)s1 * 128 + t4]);
            acc.x = fmaf(w0, v0.x, acc.x); acc.y = fmaf(w0, v0.y, acc.y);
            acc.z = fmaf(w0, v0.z, acc.z); acc.w = fmaf(w0, v0.w, acc.w);
            acc.x = fmaf(w1, v1.x, acc.x); acc.y = fmaf(w1, v1.y, acc.y);
            acc.z = fmaf(w1, v1.z, acc.z); acc.w = fmaf(w1, v1.w, acc.w);
        }
        if (q < e) {
            int   s0 = __ldg(&g_src_s[q]);
            float w0 = __ldg(&g_w_s[q]);
            float4 v0 = __ldg(&x4[(size_t)s0 * 128 + t4]);
            acc.x = fmaf(w0, v0.x, acc.x); acc.y = fmaf(w0, v0.y, acc.y);
            acc.z = fmaf(w0, v0.z, acc.z); acc.w = fmaf(w0, v0.w, acc.w);
        }
        // split to bf16 hi/lo, store into A tile
        float hx = __bfloat162float(__float2bfloat16(acc.x));
        float hy = __bfloat162float(__float2bfloat16(acc.y));
        float hz = __bfloat162float(__float2bfloat16(acc.z));
        float hw = __bfloat162float(__float2bfloat16(acc.w));
        uint32_t h01 = pack_bf16(hx, hy);
        uint32_t h23 = pack_bf16(hz, hw);
        uint32_t l01 = pack_bf16(acc.x - hx, acc.y - hy);
        uint32_t l23 = pack_bf16(acc.z - hz, acc.w - hw);

        const int row  = nl * NM + (t4 >> 5);     // 0..31
        const int wrd  = row * (AST / 2) + (t4 & 31) * 2;
        *reinterpret_cast<uint2*>(&Ah[wrd]) = make_uint2(h01, h23);
        *reinterpret_cast<uint2*>(&Al[wrd]) = make_uint2(l01, l23);
    }
    __syncthreads();

    // ---- Phase 2: GEMM via mma.sync. warp tile: rows (wid&1)*16, cols (wid>>1)*32 ----
    {
        const int g = lane >> 2, t = lane & 3;
        const int rb = wid & 1, cq = wid >> 1;
        float c[4][4];
#pragma unroll
        for (int nt = 0; nt < 4; nt++)
#pragma unroll
            for (int j = 0; j < 4; j++) c[nt][j] = 0.f;

#pragma unroll
        for (int kt = 0; kt < 8; kt++) {
            const int aw = (rb * 16 + g) * 68 + kt * 8 + t;
            uint32_t a0h = Ah[aw],        a1h = Ah[aw + 8 * 68];
            uint32_t a2h = Ah[aw + 4],    a3h = Ah[aw + 8 * 68 + 4];
            uint32_t a0l = Al[aw],        a1l = Al[aw + 8 * 68];
            uint32_t a2l = Al[aw + 4],    a3l = Al[aw + 8 * 68 + 4];
#pragma unroll
            for (int nt = 0; nt < 4; nt++) {
                const int bw = (cq * 32 + nt * 8 + g) * 68 + kt * 8 + t;
                uint32_t b0h = Bh[bw], b1h = Bh[bw + 4];
                uint32_t b0l = Bl[bw], b1l = Bl[bw + 4];
                mma_bf16(c[nt], a0h, a1h, a2h, a3h, b0h, b1h);
                mma_bf16(c[nt], a0h, a1h, a2h, a3h, b0l, b1l);
                mma_bf16(c[nt], a0l, a1l, a2l, a3l, b0h, b1h);
            }
        }
        // stage C to smem
        const int r0 = rb * 16 + g;
#pragma unroll
        for (int nt = 0; nt < 4; nt++) {
            const int col = cq * 32 + nt * 8 + 2 * t;
            *reinterpret_cast<float2*>(&Cf[r0 * CST + col])       = make_float2(c[nt][0], c[nt][1]);
            *reinterpret_cast<float2*>(&Cf[(r0 + 8) * CST + col]) = make_float2(c[nt][2], c[nt][3]);
        }
    }
    __syncthreads();

    // ---- Phase 3: residual + LayerNorm. warp wid does rows wid*4 .. wid*4+3 ----
#pragma unroll
    for (int i = 0; i < 4; i++) {
        const int row  = wid * 4 + i;
        const size_t rowg = (size_t)cta * ROWS + row;
        float4 cv = *reinterpret_cast<float4*>(&Cf[row * CST + lane * 4]);
        float4 xv = __ldg(reinterpret_cast<const float4*>(xf) + rowg * 32 + lane);

        float y0 = fmaf(ALPHA, cv.x, xv.x);
        float y1 = fmaf(ALPHA, cv.y, xv.y);
        float y2 = fmaf(ALPHA, cv.z, xv.z);
        float y3 = fmaf(ALPHA, cv.w, xv.w);

        float s  = y0 + y1 + y2 + y3;
        float ss = y0 * y0 + y1 * y1 + y2 * y2 + y3 * y3;
#pragma unroll
        for (int o = 16; o > 0; o >>= 1) {
            s  += __shfl_xor_sync(0xFFFFFFFFu, s, o);
            ss += __shfl_xor_sync(0xFFFFFFFFu, ss, o);
        }
        const float inv_d = 1.f / (float)DD;
        float mu  = s * inv_d;
        float var = ss * inv_d - mu * mu;
        float inv = rsqrtf(var + EPS);

        float4 gm = __ldg(&gamma4[lane]);
        float4 bt = __ldg(&beta4[lane]);
        float4 o4;
        o4.x = fmaf((y0 - mu) * inv, gm.x, bt.x);
        o4.y = fmaf((y1 - mu) * inv, gm.y, bt.y);
        o4.z = fmaf((y2 - mu) * inv, gm.z, bt.z);
        o4.w = fmaf((y3 - mu) * inv, gm.w, bt.w);
        out4[rowg * 32 + lane] = o4;
    }
}

// ---------------------------------------------------------------------------
extern "C" void kernel_launch(void* const* d_in, const int* in_sizes, int n_in,
                              void* d_out, int out_size) {
    const float* multimodal = (const float*)d_in[0];
    const int*   edge_src   = (const int*)d_in[1];
    const int*   edge_dst   = (const int*)d_in[2];
    const float* edge_w     = (const float*)d_in[3];
    const float* W          = (const float*)d_in[4];
    const float* gamma      = (const float*)d_in[5];
    const float* beta       = (const float*)d_in[6];
    float* out = (float*)d_out;

    cudaFuncSetAttribute(fused_kernel, cudaFuncAttributeMaxDynamicSharedMemorySize,
                         SMEM_TOTAL);

    const int SCAN_BLOCKS = (NN + 1023) / 1024;  // 49

    zero_counts_kernel<<<(NN + 255) / 256, 256>>>();
    pack_B_kernel<<<(DD * BST + 255) / 256, 256>>>(W);
    hist_kernel<<<(NE + 255) / 256, 256>>>(edge_dst);
    scan1_kernel<<<SCAN_BLOCKS, 1024>>>();
    scan2_kernel<<<1, 64>>>(SCAN_BLOCKS);
    scan3_kernel<<<SCAN_BLOCKS, 1024>>>();
    fill_csr_kernel<<<(NE + 255) / 256, 256>>>(edge_src, edge_dst, edge_w);

    fused_kernel<<<NCTA, THREADS, SMEM_TOTAL>>>(
        (const float4*)multimodal, multimodal,
        (const float4*)gamma, (const float4*)beta,
        (float4*)out);
}

// round 8
// speedup vs baseline: 2.7786x; 1.9684x over previous
#include <cuda_runtime.h>
#include <cuda_fp16.h>
#include <cuda_bf16.h>
#include <cstdint>

#define NN 50000
#define NM 4
#define DD 128
#define NE 800000
#define ALPHA 0.05f
#define EPS 1e-5f

#define TOTROWS (NN * NM)            // 200000
#define BST 136                      // B^T row stride in bf16 (68 u32 words)
#define CST 132                      // C staging row stride (floats)

// GEMM+LN kernel geometry
#define P_ROWS 128                   // rows per CTA
#define P_CTAS ((TOTROWS + P_ROWS - 1) / P_ROWS)   // 1563
#define AROWS_PAD (P_CTAS * P_ROWS)                // 200064 (padded scratch rows)
#define SMEM_P 69632                 // Bh(34816) + Bl(34816); C overlays (67584)

// ---------------------------------------------------------------------------
// Device globals (no runtime allocation)
// ---------------------------------------------------------------------------
__device__ int   g_count[NN];
__device__ int   g_off[NN + 1];
__device__ int   g_cursor[NN];
__device__ int   g_src_s[NE];
__device__ float g_w_s[NE];
__device__ int   g_bsum[64];
__device__ int   g_bbase[64];
__device__ __half g_xh[(size_t)NN * NM * DD];                  // fp16 x, 51.2 MB
__device__ __align__(16) __nv_bfloat16 g_Bt_hi[DD * BST];      // W^T hi, padded
__device__ __align__(16) __nv_bfloat16 g_Bt_lo[DD * BST];      // W^T lo
// agg scratch: per row 64 words, each stored as uint2 (hi_word, lo_word) -> 102.4 MB
__device__ __align__(16) uint2 g_A[(size_t)AROWS_PAD * 64];

// ---------------------------------------------------------------------------
// CSR build (known good)
// ---------------------------------------------------------------------------
__global__ void prep_kernel(const float* __restrict__ W) {
    int i = blockIdx.x * blockDim.x + threadIdx.x;
    if (i < NN) g_count[i] = 0;
    if (i < DD * BST) {                       // pack B = W^T into hi/lo bf16
        int n = i / BST, k = i % BST;
        float v = (k < DD) ? W[k * DD + n] : 0.f;
        __nv_bfloat16 hi = __float2bfloat16(v);
        g_Bt_hi[i] = hi;
        g_Bt_lo[i] = __float2bfloat16(v - __bfloat162float(hi));
    }
}
__global__ void convert_x_kernel(const float2* __restrict__ xf2) {
    int i = blockIdx.x * blockDim.x + threadIdx.x;
    if (i < NN * NM * DD / 2)
        reinterpret_cast<__half2*>(g_xh)[i] = __float22half2_rn(xf2[i]);
}
__global__ void hist_kernel(const int* __restrict__ dst) {
    int e = blockIdx.x * blockDim.x + threadIdx.x;
    if (e < NE) atomicAdd(&g_count[dst[e]], 1);
}
__global__ void __launch_bounds__(1024) scan1_kernel() {
    __shared__ int s[1024];
    int i = blockIdx.x * 1024 + threadIdx.x;
    int v = (i < NN) ? g_count[i] : 0;
    s[threadIdx.x] = v;
    __syncthreads();
#pragma unroll
    for (int o = 1; o < 1024; o <<= 1) {
        int t = (threadIdx.x >= o) ? s[threadIdx.x - o] : 0;
        __syncthreads();
        s[threadIdx.x] += t;
        __syncthreads();
    }
    if (i < NN) g_off[i] = s[threadIdx.x] - v;
    if (threadIdx.x == 1023) g_bsum[blockIdx.x] = s[1023];
}
__global__ void scan2_kernel(int nblocks) {
    __shared__ int s[64];
    int v = (threadIdx.x < nblocks) ? g_bsum[threadIdx.x] : 0;
    s[threadIdx.x] = v;
    __syncthreads();
#pragma unroll
    for (int o = 1; o < 64; o <<= 1) {
        int t = (threadIdx.x >= o) ? s[threadIdx.x - o] : 0;
        __syncthreads();
        s[threadIdx.x] += t;
        __syncthreads();
    }
    g_bbase[threadIdx.x] = s[threadIdx.x] - v;
    if (threadIdx.x == 0) g_off[NN] = s[63];
}
__global__ void __launch_bounds__(1024) scan3_kernel() {
    int i = blockIdx.x * 1024 + threadIdx.x;
    if (i < NN) {
        int o = g_off[i] + g_bbase[blockIdx.x];
        g_off[i] = o;
        g_cursor[i] = o;
    }
}
__global__ void fill_csr_kernel(const int* __restrict__ src,
                                const int* __restrict__ dst,
                                const float* __restrict__ w) {
    int e = blockIdx.x * blockDim.x + threadIdx.x;
    if (e < NE) {
        int t = dst[e];
        int pos = atomicAdd(&g_cursor[t], 1);
        g_src_s[pos] = src[e];
        g_w_s[pos]  = w[e];
    }
}

// ---------------------------------------------------------------------------
// Gather kernel: one CTA (128 thr) per node, R4's proven high-occupancy shape.
// Reads fp16 x rows; writes bf16 hi/lo interleaved fragment words to g_A.
// Thread t covers flat cols 4t..4t+3 -> row = node*4 + (t>>5), words 2*(t&31)..+1
// ---------------------------------------------------------------------------
__global__ void __launch_bounds__(128) gather_kernel() {
    const int node = blockIdx.x;
    const int t    = threadIdx.x;
    const int mod  = t >> 5;
    const int l4   = t & 31;

    const int b = g_off[node], e = g_off[node + 1];
    float4 acc = make_float4(0.f, 0.f, 0.f, 0.f);
    const uint2* xh2 = reinterpret_cast<const uint2*>(g_xh);
    int q = b;
    for (; q + 1 < e; q += 2) {
        int   s0 = __ldg(&g_src_s[q]);
        int   s1 = __ldg(&g_src_s[q + 1]);
        float w0 = __ldg(&g_w_s[q]);
        float w1 = __ldg(&g_w_s[q + 1]);
        uint2 v0 = __ldg(&xh2[(size_t)s0 * 128 + t]);
        uint2 v1 = __ldg(&xh2[(size_t)s1 * 128 + t]);
        float2 a01 = __half22float2(*reinterpret_cast<__half2*>(&v0.x));
        float2 a23 = __half22float2(*reinterpret_cast<__half2*>(&v0.y));
        float2 b01 = __half22float2(*reinterpret_cast<__half2*>(&v1.x));
        float2 b23 = __half22float2(*reinterpret_cast<__half2*>(&v1.y));
        acc.x = fmaf(w0, a01.x, acc.x); acc.y = fmaf(w0, a01.y, acc.y);
        acc.z = fmaf(w0, a23.x, acc.z); acc.w = fmaf(w0, a23.y, acc.w);
        acc.x = fmaf(w1, b01.x, acc.x); acc.y = fmaf(w1, b01.y, acc.y);
        acc.z = fmaf(w1, b23.x, acc.z); acc.w = fmaf(w1, b23.y, acc.w);
    }
    if (q < e) {
        int   s0 = __ldg(&g_src_s[q]);
        float w0 = __ldg(&g_w_s[q]);
        uint2 v0 = __ldg(&xh2[(size_t)s0 * 128 + t]);
        float2 a01 = __half22float2(*reinterpret_cast<__half2*>(&v0.x));
        float2 a23 = __half22float2(*reinterpret_cast<__half2*>(&v0.y));
        acc.x = fmaf(w0, a01.x, acc.x); acc.y = fmaf(w0, a01.y, acc.y);
        acc.z = fmaf(w0, a23.x, acc.z); acc.w = fmaf(w0, a23.y, acc.w);
    }

    // bf16 hi/lo split -> interleaved words {h01, l01, h23, l23}
    float hx = __bfloat162float(__float2bfloat16(acc.x));
    float hy = __bfloat162float(__float2bfloat16(acc.y));
    float hz = __bfloat162float(__float2bfloat16(acc.z));
    float hw = __bfloat162float(__float2bfloat16(acc.w));
    __nv_bfloat162 h01 = __floats2bfloat162_rn(hx, hy);
    __nv_bfloat162 h23 = __floats2bfloat162_rn(hz, hw);
    __nv_bfloat162 l01 = __floats2bfloat162_rn(acc.x - hx, acc.y - hy);
    __nv_bfloat162 l23 = __floats2bfloat162_rn(acc.z - hz, acc.w - hw);

    uint4 pkt;
    pkt.x = *reinterpret_cast<uint32_t*>(&h01);
    pkt.y = *reinterpret_cast<uint32_t*>(&l01);
    pkt.z = *reinterpret_cast<uint32_t*>(&h23);
    pkt.w = *reinterpret_cast<uint32_t*>(&l23);

    const size_t row = (size_t)node * NM + mod;
    *reinterpret_cast<uint4*>(&g_A[row * 64 + 2 * l4]) = pkt;
}

// ---------------------------------------------------------------------------
// mma.sync bf16 (baseline sm_80+ — compiles on plain compute_103)
// ---------------------------------------------------------------------------
__device__ __forceinline__ void mma_bf16(float c[4],
                                         uint32_t a0, uint32_t a1, uint32_t a2, uint32_t a3,
                                         uint32_t b0, uint32_t b1) {
    asm volatile(
        "mma.sync.aligned.m16n8k16.row.col.f32.bf16.bf16.f32 "
        "{%0,%1,%2,%3}, {%4,%5,%6,%7}, {%8,%9}, {%0,%1,%2,%3};"
        : "+f"(c[0]), "+f"(c[1]), "+f"(c[2]), "+f"(c[3])
        : "r"(a0), "r"(a1), "r"(a2), "r"(a3), "r"(b0), "r"(b1));
}

// ---------------------------------------------------------------------------
// GEMM + residual + LN kernel. 1563 CTAs x 256 thr, 128 rows per CTA.
// Warp w: rows w*16..w*16+15, all 128 cols. A fragments from global (uint2
// hi/lo interleaved); B hi/lo in smem; C staged over the dead B region.
// ---------------------------------------------------------------------------
__global__ void __launch_bounds__(256, 2) gemmln_kernel(
    const float*  __restrict__ xf,
    const float4* __restrict__ gamma4,
    const float4* __restrict__ beta4,
    float4* __restrict__ out4)
{
    extern __shared__ char sm[];
    uint32_t* Bh = reinterpret_cast<uint32_t*>(sm);            // [128][68]
    uint32_t* Bl = reinterpret_cast<uint32_t*>(sm + 34816);
    float*    Cf = reinterpret_cast<float*>(sm);               // overlay after mma

    const int tid  = threadIdx.x;
    const int wid  = tid >> 5;
    const int lane = tid & 31;
    const int g    = lane >> 2;
    const int t    = lane & 3;

    // ---- copy B hi/lo to smem ----
    {
        const uint4* sh = reinterpret_cast<const uint4*>(g_Bt_hi);
        const uint4* sl = reinterpret_cast<const uint4*>(g_Bt_lo);
        uint4* dh = reinterpret_cast<uint4*>(Bh);
        uint4* dl = reinterpret_cast<uint4*>(Bl);
        const int n16 = DD * BST * 2 / 16;   // 2176
        for (int i = tid; i < n16; i += 256) { dh[i] = sh[i]; dl[i] = sl[i]; }
    }
    __syncthreads();

    const size_t rowbase = (size_t)blockIdx.x * P_ROWS;
    const int r0 = wid * 16;

    float c[16][4];
#pragma unroll
    for (int nt = 0; nt < 16; nt++)
#pragma unroll
        for (int j = 0; j < 4; j++) c[nt][j] = 0.f;

#pragma unroll
    for (int kt = 0; kt < 8; kt++) {
        const size_t ra = (rowbase + r0 + g) * 64 + kt * 8 + t;
        const size_t rb = (rowbase + r0 + g + 8) * 64 + kt * 8 + t;
        uint2 a0 = __ldg(&g_A[ra]);
        uint2 a1 = __ldg(&g_A[rb]);
        uint2 a2 = __ldg(&g_A[ra + 4]);
        uint2 a3 = __ldg(&g_A[rb + 4]);
#pragma unroll
        for (int nt = 0; nt < 16; nt++) {
            const int bw = (nt * 8 + g) * 68 + kt * 8 + t;
            uint32_t b0h = Bh[bw], b1h = Bh[bw + 4];
            uint32_t b0l = Bl[bw], b1l = Bl[bw + 4];
            mma_bf16(c[nt], a0.x, a1.x, a2.x, a3.x, b0h, b1h);
            mma_bf16(c[nt], a0.x, a1.x, a2.x, a3.x, b0l, b1l);
            mma_bf16(c[nt], a0.y, a1.y, a2.y, a3.y, b0h, b1h);
        }
    }
    __syncthreads();   // all warps done reading B -> safe to overlay C

    // ---- stage C ----
    {
        const int rg = r0 + g;
#pragma unroll
        for (int nt = 0; nt < 16; nt++) {
            const int col = nt * 8 + 2 * t;
            *reinterpret_cast<float2*>(&Cf[rg * CST + col])       = make_float2(c[nt][0], c[nt][1]);
            *reinterpret_cast<float2*>(&Cf[(rg + 8) * CST + col]) = make_float2(c[nt][2], c[nt][3]);
        }
    }
    __syncthreads();

    // ---- residual + LayerNorm: warp wid handles rows wid*16 .. wid*16+15 ----
#pragma unroll
    for (int i = 0; i < 16; i++) {
        const int row = wid * 16 + i;
        const size_t grow = rowbase + row;
        if (grow >= TOTROWS) break;
        float4 cv = *reinterpret_cast<float4*>(&Cf[row * CST + lane * 4]);
        float4 xv = __ldg(reinterpret_cast<const float4*>(xf) + grow * 32 + lane);

        float y0 = fmaf(ALPHA, cv.x, xv.x);
        float y1 = fmaf(ALPHA, cv.y, xv.y);
        float y2 = fmaf(ALPHA, cv.z, xv.z);
        float y3 = fmaf(ALPHA, cv.w, xv.w);

        float s  = y0 + y1 + y2 + y3;
        float ss = y0 * y0 + y1 * y1 + y2 * y2 + y3 * y3;
#pragma unroll
        for (int o = 16; o > 0; o >>= 1) {
            s  += __shfl_xor_sync(0xFFFFFFFFu, s, o);
            ss += __shfl_xor_sync(0xFFFFFFFFu, ss, o);
        }
        const float inv_d = 1.f / (float)DD;
        float mu  = s * inv_d;
        float var = ss * inv_d - mu * mu;
        float inv = rsqrtf(var + EPS);

        float4 gm = __ldg(&gamma4[lane]);
        float4 bt = __ldg(&beta4[lane]);
        float4 o4;
        o4.x = fmaf((y0 - mu) * inv, gm.x, bt.x);
        o4.y = fmaf((y1 - mu) * inv, gm.y, bt.y);
        o4.z = fmaf((y2 - mu) * inv, gm.z, bt.z);
        o4.w = fmaf((y3 - mu) * inv, gm.w, bt.w);
        out4[grow * 32 + lane] = o4;
    }
}

// ---------------------------------------------------------------------------
extern "C" void kernel_launch(void* const* d_in, const int* in_sizes, int n_in,
                              void* d_out, int out_size) {
    const float* multimodal = (const float*)d_in[0];
    const int*   edge_src   = (const int*)d_in[1];
    const int*   edge_dst   = (const int*)d_in[2];
    const float* edge_w     = (const float*)d_in[3];
    const float* W          = (const float*)d_in[4];
    const float* gamma      = (const float*)d_in[5];
    const float* beta       = (const float*)d_in[6];
    float* out = (float*)d_out;

    cudaFuncSetAttribute(gemmln_kernel, cudaFuncAttributeMaxDynamicSharedMemorySize,
                         SMEM_P);

    const int SCAN_BLOCKS = (NN + 1023) / 1024;  // 49

    prep_kernel<<<(NN + 255) / 256, 256>>>(W);
    convert_x_kernel<<<(NN * NM * DD / 2 + 255) / 256, 256>>>((const float2*)multimodal);
    hist_kernel<<<(NE + 255) / 256, 256>>>(edge_dst);
    scan1_kernel<<<SCAN_BLOCKS, 1024>>>();
    scan2_kernel<<<1, 64>>>(SCAN_BLOCKS);
    scan3_kernel<<<SCAN_BLOCKS, 1024>>>();
    fill_csr_kernel<<<(NE + 255) / 256, 256>>>(edge_src, edge_dst, edge_w);

    gather_kernel<<<NN, 128>>>();
    gemmln_kernel<<<P_CTAS, 256, SMEM_P>>>(
        multimodal, (const float4*)gamma, (const float4*)beta, (float4*)out);
}

// round 9
// speedup vs baseline: 3.0144x; 1.0849x over previous
#include <cuda_runtime.h>
#include <cuda_fp16.h>
#include <cstdint>

#define NN 50000
#define NM 4
#define DD 128
#define NE 800000
#define ALPHA 0.05f
#define EPS 1e-5f

#define TOTROWS (NN * NM)            // 200000
#define BST 136                      // B^T row stride in fp16 (68 u32 words)
#define CST 132                      // C staging row stride (floats)

// GEMM+LN kernel geometry
#define P_ROWS 128
#define P_CTAS ((TOTROWS + P_ROWS - 1) / P_ROWS)   // 1563
#define AROWS_PAD (P_CTAS * P_ROWS)                // 200064
#define SMEM_P 69632                 // Bh(34816)+Bl(34816); C overlays (67584)

// ---------------------------------------------------------------------------
// Device globals
// ---------------------------------------------------------------------------
__device__ int   g_count[NN];
__device__ int   g_off[NN + 1];
__device__ int   g_cursor[NN];
__device__ int   g_src_s[NE];
__device__ float g_w_s[NE];
__device__ int   g_bsum[64];
__device__ int   g_bbase[64];
__device__ __half g_xh[(size_t)NN * NM * DD];              // fp16 x, 51.2 MB
__device__ __align__(16) __half g_Bt_hi[DD * BST];         // W^T hi (fp16)
__device__ __align__(16) __half g_Bt_lo[DD * BST];         // W^T lo (fp16)
// agg scratch: fp16, 64 u32 words per row -> 51.2 MB
__device__ __align__(16) uint32_t g_A[(size_t)AROWS_PAD * 64];

// ---------------------------------------------------------------------------
// Merged prologue: zero counts + pack B(fp16 hi/lo) + convert x->fp16 + hist
// ---------------------------------------------------------------------------
__global__ void prep_all_kernel(const float* __restrict__ W,
                                const float2* __restrict__ xf2,
                                const int* __restrict__ dst) {
    int i = blockIdx.x * blockDim.x + threadIdx.x;
    if (i < NN) g_count[i] = 0;
    if (i < DD * BST) {
        int n = i / BST, k = i % BST;
        float v = (k < DD) ? W[k * DD + n] : 0.f;
        __half hi = __float2half_rn(v);
        g_Bt_hi[i] = hi;
        g_Bt_lo[i] = __float2half_rn(v - __half2float(hi));
    }
    if (i < NE) atomicAdd(&g_count[dst[i]], 1);   // note: counts zeroed below via separate pass ordering
    if (i < NN * NM * DD / 2)
        reinterpret_cast<__half2*>(g_xh)[i] = __float22half2_rn(xf2[i]);
}

// hist must run after counts are zeroed -> do zero in its own tiny kernel
__global__ void zero_counts_kernel() {
    int i = blockIdx.x * blockDim.x + threadIdx.x;
    if (i < NN) g_count[i] = 0;
}
__global__ void prep_conv_kernel(const float* __restrict__ W,
                                 const float2* __restrict__ xf2,
                                 const int* __restrict__ dst) {
    int i = blockIdx.x * blockDim.x + threadIdx.x;
    if (i < DD * BST) {
        int n = i / BST, k = i % BST;
        float v = (k < DD) ? W[k * DD + n] : 0.f;
        __half hi = __float2half_rn(v);
        g_Bt_hi[i] = hi;
        g_Bt_lo[i] = __float2half_rn(v - __half2float(hi));
    }
    if (i < NE) atomicAdd(&g_count[dst[i]], 1);
    if (i < NN * NM * DD / 2)
        reinterpret_cast<__half2*>(g_xh)[i] = __float22half2_rn(xf2[i]);
}

__global__ void __launch_bounds__(1024) scan1_kernel() {
    __shared__ int s[1024];
    int i = blockIdx.x * 1024 + threadIdx.x;
    int v = (i < NN) ? g_count[i] : 0;
    s[threadIdx.x] = v;
    __syncthreads();
#pragma unroll
    for (int o = 1; o < 1024; o <<= 1) {
        int t = (threadIdx.x >= o) ? s[threadIdx.x - o] : 0;
        __syncthreads();
        s[threadIdx.x] += t;
        __syncthreads();
    }
    if (i < NN) g_off[i] = s[threadIdx.x] - v;
    if (threadIdx.x == 1023) g_bsum[blockIdx.x] = s[1023];
}
__global__ void scan2_kernel(int nblocks) {
    __shared__ int s[64];
    int v = (threadIdx.x < nblocks) ? g_bsum[threadIdx.x] : 0;
    s[threadIdx.x] = v;
    __syncthreads();
#pragma unroll
    for (int o = 1; o < 64; o <<= 1) {
        int t = (threadIdx.x >= o) ? s[threadIdx.x - o] : 0;
        __syncthreads();
        s[threadIdx.x] += t;
        __syncthreads();
    }
    g_bbase[threadIdx.x] = s[threadIdx.x] - v;
    if (threadIdx.x == 0) g_off[NN] = s[63];
}
__global__ void __launch_bounds__(1024) scan3_kernel() {
    int i = blockIdx.x * 1024 + threadIdx.x;
    if (i < NN) {
        int o = g_off[i] + g_bbase[blockIdx.x];
        g_off[i] = o;
        g_cursor[i] = o;
    }
}
__global__ void fill_csr_kernel(const int* __restrict__ src,
                                const int* __restrict__ dst,
                                const float* __restrict__ w) {
    int e = blockIdx.x * blockDim.x + threadIdx.x;
    if (e < NE) {
        int t = dst[e];
        int pos = atomicAdd(&g_cursor[t], 1);
        g_src_s[pos] = src[e];
        g_w_s[pos]  = w[e];
    }
}

// ---------------------------------------------------------------------------
// Gather: one CTA (128 thr) per node. Reads fp16 x rows, writes fp16 agg row.
// Thread t covers flat cols 4t..4t+3 -> words 2*(t&31), 2*(t&31)+1 (one uint2).
// ---------------------------------------------------------------------------
__global__ void __launch_bounds__(128) gather_kernel() {
    const int node = blockIdx.x;
    const int t    = threadIdx.x;
    const int mod  = t >> 5;
    const int l4   = t & 31;

    const int b = g_off[node], e = g_off[node + 1];
    float4 acc = make_float4(0.f, 0.f, 0.f, 0.f);
    const uint2* xh2 = reinterpret_cast<const uint2*>(g_xh);
    int q = b;
    for (; q + 1 < e; q += 2) {
        int   s0 = __ldg(&g_src_s[q]);
        int   s1 = __ldg(&g_src_s[q + 1]);
        float w0 = __ldg(&g_w_s[q]);
        float w1 = __ldg(&g_w_s[q + 1]);
        uint2 v0 = __ldg(&xh2[(size_t)s0 * 128 + t]);
        uint2 v1 = __ldg(&xh2[(size_t)s1 * 128 + t]);
        float2 a01 = __half22float2(*reinterpret_cast<__half2*>(&v0.x));
        float2 a23 = __half22float2(*reinterpret_cast<__half2*>(&v0.y));
        float2 b01 = __half22float2(*reinterpret_cast<__half2*>(&v1.x));
        float2 b23 = __half22float2(*reinterpret_cast<__half2*>(&v1.y));
        acc.x = fmaf(w0, a01.x, acc.x); acc.y = fmaf(w0, a01.y, acc.y);
        acc.z = fmaf(w0, a23.x, acc.z); acc.w = fmaf(w0, a23.y, acc.w);
        acc.x = fmaf(w1, b01.x, acc.x); acc.y = fmaf(w1, b01.y, acc.y);
        acc.z = fmaf(w1, b23.x, acc.z); acc.w = fmaf(w1, b23.y, acc.w);
    }
    if (q < e) {
        int   s0 = __ldg(&g_src_s[q]);
        float w0 = __ldg(&g_w_s[q]);
        uint2 v0 = __ldg(&xh2[(size_t)s0 * 128 + t]);
        float2 a01 = __half22float2(*reinterpret_cast<__half2*>(&v0.x));
        float2 a23 = __half22float2(*reinterpret_cast<__half2*>(&v0.y));
        acc.x = fmaf(w0, a01.x, acc.x); acc.y = fmaf(w0, a01.y, acc.y);
        acc.z = fmaf(w0, a23.x, acc.z); acc.w = fmaf(w0, a23.y, acc.w);
    }

    __half2 h01 = __float22half2_rn(make_float2(acc.x, acc.y));
    __half2 h23 = __float22half2_rn(make_float2(acc.z, acc.w));
    uint2 pkt;
    pkt.x = *reinterpret_cast<uint32_t*>(&h01);
    pkt.y = *reinterpret_cast<uint32_t*>(&h23);

    const size_t row = (size_t)node * NM + mod;
    *reinterpret_cast<uint2*>(&g_A[row * 64 + 2 * l4]) = pkt;
}

// ---------------------------------------------------------------------------
// mma.sync fp16 (sm_80 baseline — compiles on plain compute_103)
// ---------------------------------------------------------------------------
__device__ __forceinline__ void mma_f16(float c[4],
                                        uint32_t a0, uint32_t a1, uint32_t a2, uint32_t a3,
                                        uint32_t b0, uint32_t b1) {
    asm volatile(
        "mma.sync.aligned.m16n8k16.row.col.f32.f16.f16.f32 "
        "{%0,%1,%2,%3}, {%4,%5,%6,%7}, {%8,%9}, {%0,%1,%2,%3};"
        : "+f"(c[0]), "+f"(c[1]), "+f"(c[2]), "+f"(c[3])
        : "r"(a0), "r"(a1), "r"(a2), "r"(a3), "r"(b0), "r"(b1));
}

// ---------------------------------------------------------------------------
// GEMM + residual + LN. 1563 CTAs x 256 thr, 128 rows/CTA.
// Warp w: rows w*16..w*16+15, all 128 cols. 2 MMAs per tile (B hi + B lo).
// ---------------------------------------------------------------------------
__global__ void __launch_bounds__(256, 2) gemmln_kernel(
    const float*  __restrict__ xf,
    const float4* __restrict__ gamma4,
    const float4* __restrict__ beta4,
    float4* __restrict__ out4)
{
    extern __shared__ char sm[];
    uint32_t* Bh = reinterpret_cast<uint32_t*>(sm);            // [128][68] words
    uint32_t* Bl = reinterpret_cast<uint32_t*>(sm + 34816);
    float*    Cf = reinterpret_cast<float*>(sm);               // overlay after mma

    const int tid  = threadIdx.x;
    const int wid  = tid >> 5;
    const int lane = tid & 31;
    const int g    = lane >> 2;
    const int t    = lane & 3;

    {
        const uint4* sh = reinterpret_cast<const uint4*>(g_Bt_hi);
        const uint4* sl = reinterpret_cast<const uint4*>(g_Bt_lo);
        uint4* dh = reinterpret_cast<uint4*>(Bh);
        uint4* dl = reinterpret_cast<uint4*>(Bl);
        const int n16 = DD * BST * 2 / 16;   // 2176
        for (int i = tid; i < n16; i += 256) { dh[i] = sh[i]; dl[i] = sl[i]; }
    }
    __syncthreads();

    const size_t rowbase = (size_t)blockIdx.x * P_ROWS;
    const int r0 = wid * 16;

    float c[16][4];
#pragma unroll
    for (int nt = 0; nt < 16; nt++)
#pragma unroll
        for (int j = 0; j < 4; j++) c[nt][j] = 0.f;

#pragma unroll
    for (int kt = 0; kt < 8; kt++) {
        const size_t ra = (rowbase + r0 + g) * 64 + kt * 8 + t;
        const size_t rb = (rowbase + r0 + g + 8) * 64 + kt * 8 + t;
        uint32_t a0 = __ldg(&g_A[ra]);
        uint32_t a1 = __ldg(&g_A[rb]);
        uint32_t a2 = __ldg(&g_A[ra + 4]);
        uint32_t a3 = __ldg(&g_A[rb + 4]);
#pragma unroll
        for (int nt = 0; nt < 16; nt++) {
            const int bw = (nt * 8 + g) * 68 + kt * 8 + t;
            uint32_t b0h = Bh[bw], b1h = Bh[bw + 4];
            uint32_t b0l = Bl[bw], b1l = Bl[bw + 4];
            mma_f16(c[nt], a0, a1, a2, a3, b0h, b1h);
            mma_f16(c[nt], a0, a1, a2, a3, b0l, b1l);
        }
    }
    __syncthreads();   // B reads done -> overlay C

    {
        const int rg = r0 + g;
#pragma unroll
        for (int nt = 0; nt < 16; nt++) {
            const int col = nt * 8 + 2 * t;
            *reinterpret_cast<float2*>(&Cf[rg * CST + col])       = make_float2(c[nt][0], c[nt][1]);
            *reinterpret_cast<float2*>(&Cf[(rg + 8) * CST + col]) = make_float2(c[nt][2], c[nt][3]);
        }
    }
    __syncthreads();

#pragma unroll
    for (int i = 0; i < 16; i++) {
        const int row = wid * 16 + i;
        const size_t grow = rowbase + row;
        if (grow >= TOTROWS) break;
        float4 cv = *reinterpret_cast<float4*>(&Cf[row * CST + lane * 4]);
        float4 xv = __ldg(reinterpret_cast<const float4*>(xf) + grow * 32 + lane);

        float y0 = fmaf(ALPHA, cv.x, xv.x);
        float y1 = fmaf(ALPHA, cv.y, xv.y);
        float y2 = fmaf(ALPHA, cv.z, xv.z);
        float y3 = fmaf(ALPHA, cv.w, xv.w);

        float s  = y0 + y1 + y2 + y3;
        float ss = y0 * y0 + y1 * y1 + y2 * y2 + y3 * y3;
#pragma unroll
        for (int o = 16; o > 0; o >>= 1) {
            s  += __shfl_xor_sync(0xFFFFFFFFu, s, o);
            ss += __shfl_xor_sync(0xFFFFFFFFu, ss, o);
        }
        const float inv_d = 1.f / (float)DD;
        float mu  = s * inv_d;
        float var = ss * inv_d - mu * mu;
        float inv = rsqrtf(var + EPS);

        float4 gm = __ldg(&gamma4[lane]);
        float4 bt = __ldg(&beta4[lane]);
        float4 o4;
        o4.x = fmaf((y0 - mu) * inv, gm.x, bt.x);
        o4.y = fmaf((y1 - mu) * inv, gm.y, bt.y);
        o4.z = fmaf((y2 - mu) * inv, gm.z, bt.z);
        o4.w = fmaf((y3 - mu) * inv, gm.w, bt.w);
        out4[grow * 32 + lane] = o4;
    }
}

// ---------------------------------------------------------------------------
extern "C" void kernel_launch(void* const* d_in, const int* in_sizes, int n_in,
                              void* d_out, int out_size) {
    const float* multimodal = (const float*)d_in[0];
    const int*   edge_src   = (const int*)d_in[1];
    const int*   edge_dst   = (const int*)d_in[2];
    const float* edge_w     = (const float*)d_in[3];
    const float* W          = (const float*)d_in[4];
    const float* gamma      = (const float*)d_in[5];
    const float* beta       = (const float*)d_in[6];
    float* out = (float*)d_out;

    cudaFuncSetAttribute(gemmln_kernel, cudaFuncAttributeMaxDynamicSharedMemorySize,
                         SMEM_P);

    const int SCAN_BLOCKS = (NN + 1023) / 1024;  // 49
    const int PREP_BLOCKS = (NN * NM * DD / 2 + 255) / 256;   // covers all prep jobs

    zero_counts_kernel<<<(NN + 255) / 256, 256>>>();
    prep_conv_kernel<<<PREP_BLOCKS, 256>>>(W, (const float2*)multimodal, edge_dst);
    scan1_kernel<<<SCAN_BLOCKS, 1024>>>();
    scan2_kernel<<<1, 64>>>(SCAN_BLOCKS);
    scan3_kernel<<<SCAN_BLOCKS, 1024>>>();
    fill_csr_kernel<<<(NE + 255) / 256, 256>>>(edge_src, edge_dst, edge_w);

    gather_kernel<<<NN, 128>>>();
    gemmln_kernel<<<P_CTAS, 256, SMEM_P>>>(
        multimodal, (const float4*)gamma, (const float4*)beta, (float4*)out);
}

// round 10
// speedup vs baseline: 3.1603x; 1.0484x over previous
#include <cuda_runtime.h>
#include <cuda_fp16.h>
#include <cstdint>

#define NN 50000
#define NM 4
#define DD 128
#define NE 800000
#define ALPHA 0.05f
#define EPS 1e-5f

#define TOTROWS (NN * NM)            // 200000
#define BST 136                      // B^T row stride in fp16 (68 u32 words)
#define CST 132                      // C staging row stride (floats)

#define P_ROWS 128
#define P_CTAS ((TOTROWS + P_ROWS - 1) / P_ROWS)   // 1563
#define AROWS_PAD (P_CTAS * P_ROWS)                // 200064
#define SMEM_P 69632                 // Bh(34816)+Bl(34816); C overlays (67584)

// ---------------------------------------------------------------------------
// Device globals
// ---------------------------------------------------------------------------
__device__ int   g_count[NN];        // zeroed by previous call's fill_csr (BSS-zero first call)
__device__ int   g_off[NN + 1];
__device__ int   g_cursor[NN];
__device__ uint2 g_edge[NE];         // packed (src, w-bits) sorted by dst
__device__ int   g_bsum[64];
__device__ __half g_xh[(size_t)NN * NM * DD];              // fp16 x, 51.2 MB
__device__ __align__(16) __half g_Bt_hi[DD * BST];         // W^T hi (fp16)
__device__ __align__(16) __half g_Bt_lo[DD * BST];         // W^T lo (fp16)
__device__ __align__(16) uint32_t g_A[(size_t)AROWS_PAD * 64];   // fp16 agg, 51.2 MB

// ---------------------------------------------------------------------------
// Prologue: pack B (fp16 hi/lo) + histogram dst + convert x->fp16, one kernel
// ---------------------------------------------------------------------------
__global__ void prep_conv_kernel(const float* __restrict__ W,
                                 const float2* __restrict__ xf2,
                                 const int* __restrict__ dst) {
    int i = blockIdx.x * blockDim.x + threadIdx.x;
    if (i < DD * BST) {
        int n = i / BST, k = i % BST;
        float v = (k < DD) ? W[k * DD + n] : 0.f;
        __half hi = __float2half_rn(v);
        g_Bt_hi[i] = hi;
        g_Bt_lo[i] = __float2half_rn(v - __half2float(hi));
    }
    if (i < NE) atomicAdd(&g_count[dst[i]], 1);
    if (i < NN * NM * DD / 2)
        reinterpret_cast<__half2*>(g_xh)[i] = __float22half2_rn(xf2[i]);
}

__global__ void __launch_bounds__(1024) scan1_kernel() {
    __shared__ int s[1024];
    int i = blockIdx.x * 1024 + threadIdx.x;
    int v = (i < NN) ? g_count[i] : 0;
    s[threadIdx.x] = v;
    __syncthreads();
#pragma unroll
    for (int o = 1; o < 1024; o <<= 1) {
        int t = (threadIdx.x >= o) ? s[threadIdx.x - o] : 0;
        __syncthreads();
        s[threadIdx.x] += t;
        __syncthreads();
    }
    if (i < NN) g_off[i] = s[threadIdx.x] - v;
    if (threadIdx.x == 1023) g_bsum[blockIdx.x] = s[1023];
}

// scan2+scan3 merged: each block redundantly scans the 49 block sums in smem.
__global__ void __launch_bounds__(1024) scan23_kernel() {
    __shared__ int sb[64];
    const int tid = threadIdx.x;
    if (tid < 64) sb[tid] = (tid < 49) ? g_bsum[tid] : 0;
    __syncthreads();
#pragma unroll
    for (int o = 1; o < 64; o <<= 1) {
        int t = (tid < 64 && tid >= o) ? sb[tid - o] : 0;
        __syncthreads();
        if (tid < 64) sb[tid] += t;
        __syncthreads();
    }
    const int base = (blockIdx.x > 0) ? sb[blockIdx.x - 1] : 0;   // inclusive of prev blocks
    int i = blockIdx.x * 1024 + tid;
    if (i < NN) {
        int o = g_off[i] + base;
        g_off[i] = o;
        g_cursor[i] = o;
    }
    if (blockIdx.x == 0 && tid == 0) g_off[NN] = sb[48];
}

__global__ void fill_csr_kernel(const int* __restrict__ src,
                                const int* __restrict__ dst,
                                const float* __restrict__ w) {
    int e = blockIdx.x * blockDim.x + threadIdx.x;
    if (e < NE) {
        int t = dst[e];
        int pos = atomicAdd(&g_cursor[t], 1);
        g_edge[pos] = make_uint2((uint32_t)src[e], __float_as_uint(w[e]));
    }
    // reset counts for the NEXT call (this call's scan already consumed them)
    if (e < NN) g_count[e] = 0;
}

// ---------------------------------------------------------------------------
// Gather: one CTA (128 thr) per node, edge loop unrolled x4 (MLP~4).
// Thread t covers flat cols 4t..4t+3; writes fp16 agg words 2*(t&31)..+1.
// ---------------------------------------------------------------------------
__global__ void __launch_bounds__(128) gather_kernel() {
    const int node = blockIdx.x;
    const int t    = threadIdx.x;
    const int mod  = t >> 5;
    const int l4   = t & 31;

    const int b = g_off[node], e = g_off[node + 1];
    float4 acc = make_float4(0.f, 0.f, 0.f, 0.f);
    const uint2* xh2 = reinterpret_cast<const uint2*>(g_xh);

    int q = b;
    for (; q + 3 < e; q += 4) {
        uint2 e0 = __ldg(&g_edge[q]);
        uint2 e1 = __ldg(&g_edge[q + 1]);
        uint2 e2 = __ldg(&g_edge[q + 2]);
        uint2 e3 = __ldg(&g_edge[q + 3]);
        uint2 v0 = __ldg(&xh2[(size_t)e0.x * 128 + t]);
        uint2 v1 = __ldg(&xh2[(size_t)e1.x * 128 + t]);
        uint2 v2 = __ldg(&xh2[(size_t)e2.x * 128 + t]);
        uint2 v3 = __ldg(&xh2[(size_t)e3.x * 128 + t]);
        float w0 = __uint_as_float(e0.y), w1 = __uint_as_float(e1.y);
        float w2 = __uint_as_float(e2.y), w3 = __uint_as_float(e3.y);

        float2 p, r;
        p = __half22float2(*reinterpret_cast<__half2*>(&v0.x));
        r = __half22float2(*reinterpret_cast<__half2*>(&v0.y));
        acc.x = fmaf(w0, p.x, acc.x); acc.y = fmaf(w0, p.y, acc.y);
        acc.z = fmaf(w0, r.x, acc.z); acc.w = fmaf(w0, r.y, acc.w);
        p = __half22float2(*reinterpret_cast<__half2*>(&v1.x));
        r = __half22float2(*reinterpret_cast<__half2*>(&v1.y));
        acc.x = fmaf(w1, p.x, acc.x); acc.y = fmaf(w1, p.y, acc.y);
        acc.z = fmaf(w1, r.x, acc.z); acc.w = fmaf(w1, r.y, acc.w);
        p = __half22float2(*reinterpret_cast<__half2*>(&v2.x));
        r = __half22float2(*reinterpret_cast<__half2*>(&v2.y));
        acc.x = fmaf(w2, p.x, acc.x); acc.y = fmaf(w2, p.y, acc.y);
        acc.z = fmaf(w2, r.x, acc.z); acc.w = fmaf(w2, r.y, acc.w);
        p = __half22float2(*reinterpret_cast<__half2*>(&v3.x));
        r = __half22float2(*reinterpret_cast<__half2*>(&v3.y));
        acc.x = fmaf(w3, p.x, acc.x); acc.y = fmaf(w3, p.y, acc.y);
        acc.z = fmaf(w3, r.x, acc.z); acc.w = fmaf(w3, r.y, acc.w);
    }
    for (; q < e; q++) {
        uint2 e0 = __ldg(&g_edge[q]);
        uint2 v0 = __ldg(&xh2[(size_t)e0.x * 128 + t]);
        float w0 = __uint_as_float(e0.y);
        float2 p = __half22float2(*reinterpret_cast<__half2*>(&v0.x));
        float2 r = __half22float2(*reinterpret_cast<__half2*>(&v0.y));
        acc.x = fmaf(w0, p.x, acc.x); acc.y = fmaf(w0, p.y, acc.y);
        acc.z = fmaf(w0, r.x, acc.z); acc.w = fmaf(w0, r.y, acc.w);
    }

    __half2 h01 = __float22half2_rn(make_float2(acc.x, acc.y));
    __half2 h23 = __float22half2_rn(make_float2(acc.z, acc.w));
    uint2 pkt;
    pkt.x = *reinterpret_cast<uint32_t*>(&h01);
    pkt.y = *reinterpret_cast<uint32_t*>(&h23);

    const size_t row = (size_t)node * NM + mod;
    *reinterpret_cast<uint2*>(&g_A[row * 64 + 2 * l4]) = pkt;
}

// ---------------------------------------------------------------------------
// mma.sync fp16 (sm_80 baseline)
// ---------------------------------------------------------------------------
__device__ __forceinline__ void mma_f16(float c[4],
                                        uint32_t a0, uint32_t a1, uint32_t a2, uint32_t a3,
                                        uint32_t b0, uint32_t b1) {
    asm volatile(
        "mma.sync.aligned.m16n8k16.row.col.f32.f16.f16.f32 "
        "{%0,%1,%2,%3}, {%4,%5,%6,%7}, {%8,%9}, {%0,%1,%2,%3};"
        : "+f"(c[0]), "+f"(c[1]), "+f"(c[2]), "+f"(c[3])
        : "r"(a0), "r"(a1), "r"(a2), "r"(a3), "r"(b0), "r"(b1));
}

// ---------------------------------------------------------------------------
// GEMM + residual + LN. 1563 CTAs x 256 thr, 128 rows/CTA.
// Residual x read as fp16 from g_xh (halves this kernel's DRAM read).
// ---------------------------------------------------------------------------
__global__ void __launch_bounds__(256, 2) gemmln_kernel(
    const float4* __restrict__ gamma4,
    const float4* __restrict__ beta4,
    float4* __restrict__ out4)
{
    extern __shared__ char sm[];
    uint32_t* Bh = reinterpret_cast<uint32_t*>(sm);            // [128][68] words
    uint32_t* Bl = reinterpret_cast<uint32_t*>(sm + 34816);
    float*    Cf = reinterpret_cast<float*>(sm);               // overlay after mma

    const int tid  = threadIdx.x;
    const int wid  = tid >> 5;
    const int lane = tid & 31;
    const int g    = lane >> 2;
    const int t    = lane & 3;

    {
        const uint4* sh = reinterpret_cast<const uint4*>(g_Bt_hi);
        const uint4* sl = reinterpret_cast<const uint4*>(g_Bt_lo);
        uint4* dh = reinterpret_cast<uint4*>(Bh);
        uint4* dl = reinterpret_cast<uint4*>(Bl);
        const int n16 = DD * BST * 2 / 16;   // 2176
        for (int i = tid; i < n16; i += 256) { dh[i] = sh[i]; dl[i] = sl[i]; }
    }
    __syncthreads();

    const size_t rowbase = (size_t)blockIdx.x * P_ROWS;
    const int r0 = wid * 16;

    float c[16][4];
#pragma unroll
    for (int nt = 0; nt < 16; nt++)
#pragma unroll
        for (int j = 0; j < 4; j++) c[nt][j] = 0.f;

#pragma unroll
    for (int kt = 0; kt < 8; kt++) {
        const size_t ra = (rowbase + r0 + g) * 64 + kt * 8 + t;
        const size_t rb = (rowbase + r0 + g + 8) * 64 + kt * 8 + t;
        uint32_t a0 = __ldg(&g_A[ra]);
        uint32_t a1 = __ldg(&g_A[rb]);
        uint32_t a2 = __ldg(&g_A[ra + 4]);
        uint32_t a3 = __ldg(&g_A[rb + 4]);
#pragma unroll
        for (int nt = 0; nt < 16; nt++) {
            const int bw = (nt * 8 + g) * 68 + kt * 8 + t;
            uint32_t b0h = Bh[bw], b1h = Bh[bw + 4];
            uint32_t b0l = Bl[bw], b1l = Bl[bw + 4];
            mma_f16(c[nt], a0, a1, a2, a3, b0h, b1h);
            mma_f16(c[nt], a0, a1, a2, a3, b0l, b1l);
        }
    }
    __syncthreads();   // B reads done -> overlay C

    {
        const int rg = r0 + g;
#pragma unroll
        for (int nt = 0; nt < 16; nt++) {
            const int col = nt * 8 + 2 * t;
            *reinterpret_cast<float2*>(&Cf[rg * CST + col])       = make_float2(c[nt][0], c[nt][1]);
            *reinterpret_cast<float2*>(&Cf[(rg + 8) * CST + col]) = make_float2(c[nt][2], c[nt][3]);
        }
    }
    __syncthreads();

    const uint2* xh2 = reinterpret_cast<const uint2*>(g_xh);
#pragma unroll
    for (int i = 0; i < 16; i++) {
        const int row = wid * 16 + i;
        const size_t grow = rowbase + row;
        if (grow >= TOTROWS) break;
        float4 cv = *reinterpret_cast<float4*>(&Cf[row * CST + lane * 4]);
        uint2 xv2 = __ldg(&xh2[grow * 32 + lane]);
        float2 x01 = __half22float2(*reinterpret_cast<__half2*>(&xv2.x));
        float2 x23 = __half22float2(*reinterpret_cast<__half2*>(&xv2.y));

        float y0 = fmaf(ALPHA, cv.x, x01.x);
        float y1 = fmaf(ALPHA, cv.y, x01.y);
        float y2 = fmaf(ALPHA, cv.z, x23.x);
        float y3 = fmaf(ALPHA, cv.w, x23.y);

        float s  = y0 + y1 + y2 + y3;
        float ss = y0 * y0 + y1 * y1 + y2 * y2 + y3 * y3;
#pragma unroll
        for (int o = 16; o > 0; o >>= 1) {
            s  += __shfl_xor_sync(0xFFFFFFFFu, s, o);
            ss += __shfl_xor_sync(0xFFFFFFFFu, ss, o);
        }
        const float inv_d = 1.f / (float)DD;
        float mu  = s * inv_d;
        float var = ss * inv_d - mu * mu;
        float inv = rsqrtf(var + EPS);

        float4 gm = __ldg(&gamma4[lane]);
        float4 bt = __ldg(&beta4[lane]);
        float4 o4;
        o4.x = fmaf((y0 - mu) * inv, gm.x, bt.x);
        o4.y = fmaf((y1 - mu) * inv, gm.y, bt.y);
        o4.z = fmaf((y2 - mu) * inv, gm.z, bt.z);
        o4.w = fmaf((y3 - mu) * inv, gm.w, bt.w);
        out4[grow * 32 + lane] = o4;
    }
}

// ---------------------------------------------------------------------------
extern "C" void kernel_launch(void* const* d_in, const int* in_sizes, int n_in,
                              void* d_out, int out_size) {
    const float* multimodal = (const float*)d_in[0];
    const int*   edge_src   = (const int*)d_in[1];
    const int*   edge_dst   = (const int*)d_in[2];
    const float* edge_w     = (const float*)d_in[3];
    const float* W          = (const float*)d_in[4];
    const float* gamma      = (const float*)d_in[5];
    const float* beta       = (const float*)d_in[6];
    float* out = (float*)d_out;

    cudaFuncSetAttribute(gemmln_kernel, cudaFuncAttributeMaxDynamicSharedMemorySize,
                         SMEM_P);

    const int SCAN_BLOCKS = (NN + 1023) / 1024;  // 49
    const int PREP_BLOCKS = (NN * NM * DD / 2 + 255) / 256;

    prep_conv_kernel<<<PREP_BLOCKS, 256>>>(W, (const float2*)multimodal, edge_dst);
    scan1_kernel<<<SCAN_BLOCKS, 1024>>>();
    scan23_kernel<<<SCAN_BLOCKS, 1024>>>();
    fill_csr_kernel<<<(NE + 255) / 256, 256>>>(edge_src, edge_dst, edge_w);

    gather_kernel<<<NN, 128>>>();
    gemmln_kernel<<<P_CTAS, 256, SMEM_P>>>(
        (const float4*)gamma, (const float4*)beta, (float4*)out);
}